// round 5
// baseline (speedup 1.0000x reference)
#include <cuda_runtime.h>
#include <cuda_bf16.h>
#include <cstdint>

#define NEXP 8
#define DIN  1024
#define DOUT 1024
#define NTOK 8192

#define BM 128
#define BN 256
#define BK 32
#define THREADS 256

#define ROWPITCH 80                      /* 32 bf16 = 64B data, padded to 80B */
#define A_TILE_B (128 * ROWPITCH)        /* 10240 */
#define B_TILE_B (256 * ROWPITCH)        /* 20480 */
#define STAGE_B  (2 * A_TILE_B + 2 * B_TILE_B)   /* 61440: Ah Al Bh Bl */
#define NSTAGE   3
#define SMEM_BYTES (NSTAGE * STAGE_B)    /* 184320 */
#define AH_OFF   0
#define AL_OFF   A_TILE_B                /* 10240 */
#define BH_OFF   (2 * A_TILE_B)          /* 20480 */
#define BL_OFF   (2 * A_TILE_B + B_TILE_B) /* 40960 */

// ---------------- scratch (device globals; no allocation) ----------------
__device__ int   g_cnt[NEXP];
__device__ int   g_tok[NEXP * NTOK];
__device__ float g_wt [NEXP * NTOK];
__device__ __nv_bfloat16 g_xh [(size_t)NTOK * DIN];
__device__ __nv_bfloat16 g_xl [(size_t)NTOK * DIN];
__device__ __nv_bfloat16 g_hh [(size_t)NEXP * NTOK * DOUT];
__device__ __nv_bfloat16 g_hl [(size_t)NEXP * NTOK * DOUT];
__device__ __nv_bfloat16 g_W1Th[(size_t)NEXP * DIN * DOUT];
__device__ __nv_bfloat16 g_W1Tl[(size_t)NEXP * DIN * DOUT];
__device__ __nv_bfloat16 g_W2Th[(size_t)NEXP * DOUT * DOUT];
__device__ __nv_bfloat16 g_W2Tl[(size_t)NEXP * DOUT * DOUT];

// ---------------- helpers ----------------
__device__ __forceinline__ uint32_t smem_u32(const void* p) {
    uint32_t a;
    asm("{ .reg .u64 t; cvta.to.shared.u64 t, %1; cvt.u32.u64 %0, t; }" : "=r"(a) : "l"(p));
    return a;
}
__device__ __forceinline__ void cp_async16(uint32_t dst, const void* src) {
    asm volatile("cp.async.cg.shared.global [%0], [%1], 16;" :: "r"(dst), "l"(src) : "memory");
}
#define CP_COMMIT() asm volatile("cp.async.commit_group;" ::: "memory")
#define CP_WAIT1()  asm volatile("cp.async.wait_group 1;" ::: "memory")

__device__ __forceinline__ void mma_bf16(float* d, const uint32_t* a, const uint32_t* b) {
    asm volatile(
        "mma.sync.aligned.m16n8k16.row.col.f32.bf16.bf16.f32 "
        "{%0,%1,%2,%3},{%4,%5,%6,%7},{%8,%9},{%0,%1,%2,%3};"
        : "+f"(d[0]), "+f"(d[1]), "+f"(d[2]), "+f"(d[3])
        : "r"(a[0]), "r"(a[1]), "r"(a[2]), "r"(a[3]), "r"(b[0]), "r"(b[1]));
}
__device__ __forceinline__ void ldmx4(uint32_t* r, uint32_t addr) {
    asm volatile("ldmatrix.sync.aligned.m8n8.x4.shared.b16 {%0,%1,%2,%3}, [%4];"
                 : "=r"(r[0]), "=r"(r[1]), "=r"(r[2]), "=r"(r[3]) : "r"(addr));
}

// ---------------------------------------------------------------------------
__global__ void zero_kernel(float* __restrict__ out) {
    int i = blockIdx.x * blockDim.x + threadIdx.x;
    ((float4*)out)[i] = make_float4(0.f, 0.f, 0.f, 0.f);
    if (blockIdx.x == 0 && threadIdx.x < NEXP) g_cnt[threadIdx.x] = 0;
}

// ---------------------------------------------------------------------------
__global__ void gate_kernel(const float* __restrict__ x,
                            const float* __restrict__ Wg,
                            const float* __restrict__ bg) {
    int warp = (blockIdx.x * blockDim.x + threadIdx.x) >> 5;
    int lane = threadIdx.x & 31;
    if (warp >= NTOK) return;
    const float* xr = x + (size_t)warp * DIN;
    float acc[NEXP];
#pragma unroll
    for (int e = 0; e < NEXP; e++) acc[e] = 0.f;
    for (int kk = 0; kk < DIN / 32; kk++) {
        int k = kk * 32 + lane;
        float xv = xr[k];
        const float* wr = Wg + k * NEXP;
#pragma unroll
        for (int e = 0; e < NEXP; e++) acc[e] += xv * wr[e];
    }
#pragma unroll
    for (int e = 0; e < NEXP; e++)
#pragma unroll
        for (int o = 16; o > 0; o >>= 1)
            acc[e] += __shfl_xor_sync(0xffffffffu, acc[e], o);
    if (lane == 0) {
        float m = -1e30f;
#pragma unroll
        for (int e = 0; e < NEXP; e++) { acc[e] += bg[e]; m = fmaxf(m, acc[e]); }
        float s = 0.f;
#pragma unroll
        for (int e = 0; e < NEXP; e++) { acc[e] = expf(acc[e] - m); s += acc[e]; }
        float inv = 1.f / s;
        int e0 = 0, e1 = -1;
        float v0 = acc[0], v1 = -1.f;
#pragma unroll
        for (int e = 1; e < NEXP; e++) {
            float v = acc[e];
            if (v > v0)      { v1 = v0; e1 = e0; v0 = v; e0 = e; }
            else if (v > v1) { v1 = v;  e1 = e; }
        }
        int p0 = atomicAdd(&g_cnt[e0], 1);
        g_tok[e0 * NTOK + p0] = warp;  g_wt[e0 * NTOK + p0] = v0 * inv;
        int p1 = atomicAdd(&g_cnt[e1], 1);
        g_tok[e1 * NTOK + p1] = warp;  g_wt[e1 * NTOK + p1] = v1 * inv;
    }
}

// ---------------------------------------------------------------------------
__global__ void split_x_kernel(const float* __restrict__ x) {
    size_t i = ((size_t)blockIdx.x * blockDim.x + threadIdx.x) * 4;
    float4 v = *(const float4*)(x + i);
    __nv_bfloat16 h0 = __float2bfloat16(v.x), h1 = __float2bfloat16(v.y);
    __nv_bfloat16 h2 = __float2bfloat16(v.z), h3 = __float2bfloat16(v.w);
    __nv_bfloat16 l0 = __float2bfloat16(v.x - __bfloat162float(h0));
    __nv_bfloat16 l1 = __float2bfloat16(v.y - __bfloat162float(h1));
    __nv_bfloat16 l2 = __float2bfloat16(v.z - __bfloat162float(h2));
    __nv_bfloat16 l3 = __float2bfloat16(v.w - __bfloat162float(h3));
    *(__nv_bfloat162*)(g_xh + i)     = __halves2bfloat162(h0, h1);
    *(__nv_bfloat162*)(g_xh + i + 2) = __halves2bfloat162(h2, h3);
    *(__nv_bfloat162*)(g_xl + i)     = __halves2bfloat162(l0, l1);
    *(__nv_bfloat162*)(g_xl + i + 2) = __halves2bfloat162(l2, l3);
}

// ---------------------------------------------------------------------------
__global__ void transpose_split_kernel(const float* __restrict__ W,
                                       __nv_bfloat16* __restrict__ WTh,
                                       __nv_bfloat16* __restrict__ WTl) {
    __shared__ float t[32][33];
    int e = blockIdx.z;
    const float* Ws = W + ((size_t)e << 20);
    int x0 = blockIdx.x * 32, y0 = blockIdx.y * 32;
    int tx = threadIdx.x, ty = threadIdx.y;
#pragma unroll
    for (int i = 0; i < 32; i += 8)
        t[ty + i][tx] = Ws[(size_t)(y0 + ty + i) * 1024 + x0 + tx];
    __syncthreads();
#pragma unroll
    for (int i = 0; i < 32; i += 8) {
        float v = t[tx][ty + i];
        __nv_bfloat16 h = __float2bfloat16(v);
        __nv_bfloat16 l = __float2bfloat16(v - __bfloat162float(h));
        size_t o = ((size_t)e << 20) + (size_t)(x0 + ty + i) * 1024 + y0 + tx;
        WTh[o] = h;  WTl[o] = l;
    }
}

// ---------------------------------------------------------------------------
// bf16-split mma.sync GEMM: 128x256x32 tiles, 3-stage cp.async pipeline.
// 8 warps = 2(M) x 4(N), warp tile 64x64, 3 split terms (hh, hl, lh).
// ---------------------------------------------------------------------------
template <bool G2>
__global__ __launch_bounds__(THREADS, 1)
void moe_mma_kernel(const __nv_bfloat16* __restrict__ Wh,
                    const __nv_bfloat16* __restrict__ Wl,
                    const float* __restrict__ bias,
                    float* __restrict__ outp) {
    extern __shared__ char smem[];
    __shared__ int   s_tok[BM];
    __shared__ float s_wt[BM];
    __shared__ float s_bias[BN];

    const int e   = blockIdx.z;
    const int cnt = g_cnt[e];
    const int m0  = blockIdx.y * BM;
    if (m0 >= cnt) return;
    const int n0  = blockIdx.x * BN;

    const int tid  = threadIdx.x;
    const int wid  = tid >> 5;
    const int lane = tid & 31;

    if (tid < BM) {
        int ok = (m0 + tid) < cnt;
        s_tok[tid] = ok ? g_tok[e * NTOK + m0 + tid] : 0;
        s_wt[tid]  = ok ? g_wt[e * NTOK + m0 + tid] : 0.f;
    }
    s_bias[tid] = bias[e * 1024 + n0 + tid];
    __syncthreads();

    // ---- cp.async geometry: 12 ops/thread/iter ----
    // A: rows r0 = tid>>2 and r0+64, hi+lo (4 ops). B: rows rB = tid>>2 + 64k,
    // k=0..3, hi+lo (8 ops). ch = tid&3 selects the 16B chunk of the 64B row.
    const uint32_t sb = smem_u32(smem);
    const int r0 = tid >> 2;
    const int ch = tid & 3;

    const __nv_bfloat16* pA0;
    const __nv_bfloat16* pA1;
    ptrdiff_t dAl;
    if (G2) {
        pA0 = g_hh + ((size_t)e * NTOK + m0 + r0) * 1024 + ch * 8;
        pA1 = pA0 + (size_t)64 * 1024;
        dAl = g_hl - g_hh;
    } else {
        pA0 = g_xh + (size_t)s_tok[r0] * 1024 + ch * 8;
        pA1 = g_xh + (size_t)s_tok[r0 + 64] * 1024 + ch * 8;
        dAl = g_xl - g_xh;
    }
    const __nv_bfloat16* pB = Wh + (((size_t)e << 10) + n0 + r0) * 1024 + ch * 8;
    const ptrdiff_t dBl = Wl - Wh;

    const uint32_t sA = sb + r0 * ROWPITCH + ch * 16;          // Ah row r0
    const uint32_t sB = sb + BH_OFF + r0 * ROWPITCH + ch * 16; // Bh row r0

    auto issue = [&](int s, int c) {
        const uint32_t so = (uint32_t)(s * STAGE_B);
        const size_t ko = (size_t)c * BK;
        cp_async16(sA + so,                      pA0 + ko);
        cp_async16(sA + so + 64 * ROWPITCH,      pA1 + ko);
        cp_async16(sA + so + AL_OFF,             pA0 + dAl + ko);
        cp_async16(sA + so + AL_OFF + 64 * ROWPITCH, pA1 + dAl + ko);
#pragma unroll
        for (int k = 0; k < 4; k++) {
            cp_async16(sB + so + k * 64 * ROWPITCH,
                       pB + (size_t)k * 64 * 1024 + ko);
            cp_async16(sB + so + (BL_OFF - BH_OFF) + k * 64 * ROWPITCH,
                       pB + dBl + (size_t)k * 64 * 1024 + ko);
        }
    };

    float acc[2][8][8];   // [mf][nf][4] flattened as [2 mf][8 nf][... wait
    // NOTE: warp tile 64x64 -> mf 0..3, nf 0..7. Use acc[4][8][4].
    (void)acc;
    float ac[4][8][4];
#pragma unroll
    for (int a = 0; a < 4; a++)
#pragma unroll
        for (int b = 0; b < 8; b++)
#pragma unroll
            for (int c = 0; c < 4; c++) ac[a][b][c] = 0.f;

    issue(0, 0); CP_COMMIT();
    issue(1, 1); CP_COMMIT();

    const int wm = wid >> 2;             // 0..1 -> m offset 64*wm
    const int wn = wid & 3;              // 0..3 -> n offset 64*wn

    const int aRow  = wm * 64 + (lane & 7) + ((lane >> 3) & 1) * 8;
    const int aKoff = ((lane >> 4) & 1) * 16;
    const int bRow  = wn * 64 + (lane & 7) + ((lane >> 4) & 1) * 8;
    const int bKoff = ((lane >> 3) & 1) * 16;

    const int NITER = DIN / BK;          // 32
    for (int c = 0; c < NITER; c++) {
        const int s = c % NSTAGE;
        CP_WAIT1();
        __syncthreads();
        if (c + 2 < NITER) issue((c + 2) % NSTAGE, c + 2);
        CP_COMMIT();

        const uint32_t stg = sb + s * STAGE_B;
        const uint32_t Ah = stg + AH_OFF;
        const uint32_t Al = stg + AL_OFF;
        const uint32_t Bh = stg + BH_OFF;
        const uint32_t Bl = stg + BL_OFF;

#pragma unroll
        for (int ks = 0; ks < 2; ks++) {
            const uint32_t aoff = (uint32_t)(aRow * ROWPITCH + ks * 32 + aKoff);
            const uint32_t boff = (uint32_t)(bRow * ROWPITCH + ks * 32 + bKoff);
            uint32_t ah[4][4], al[4][4], bh[4][4], bl[4][4];
#pragma unroll
            for (int mf = 0; mf < 4; mf++) {
                ldmx4(ah[mf], Ah + aoff + mf * 16 * ROWPITCH);
                ldmx4(al[mf], Al + aoff + mf * 16 * ROWPITCH);
            }
#pragma unroll
            for (int np = 0; np < 4; np++) {
                ldmx4(bh[np], Bh + boff + np * 16 * ROWPITCH);
                ldmx4(bl[np], Bl + boff + np * 16 * ROWPITCH);
            }
#pragma unroll
            for (int mf = 0; mf < 4; mf++)
#pragma unroll
                for (int nf = 0; nf < 8; nf++)
                    mma_bf16(ac[mf][nf], ah[mf], &bh[nf >> 1][(nf & 1) * 2]);
#pragma unroll
            for (int mf = 0; mf < 4; mf++)
#pragma unroll
                for (int nf = 0; nf < 8; nf++)
                    mma_bf16(ac[mf][nf], ah[mf], &bl[nf >> 1][(nf & 1) * 2]);
#pragma unroll
            for (int mf = 0; mf < 4; mf++)
#pragma unroll
                for (int nf = 0; nf < 8; nf++)
                    mma_bf16(ac[mf][nf], al[mf], &bh[nf >> 1][(nf & 1) * 2]);
        }
    }

    // ---- epilogue: direct from registers (quads cover full 32B sectors) ----
    const int lr = lane >> 2;
    const int lc = (lane & 3) * 2;
#pragma unroll
    for (int mf = 0; mf < 4; mf++) {
#pragma unroll
        for (int nf = 0; nf < 8; nf++) {
            const float* d = ac[mf][nf];
            int col_l = wn * 64 + nf * 8 + lc;
            int colg  = n0 + col_l;
            float bb0 = s_bias[col_l], bb1 = s_bias[col_l + 1];
#pragma unroll
            for (int half = 0; half < 2; half++) {
                int row = wm * 64 + mf * 16 + lr + half * 8;  // local slot
                if (m0 + row >= cnt) continue;
                float v0 = d[half * 2]     + bb0;
                float v1 = d[half * 2 + 1] + bb1;
                if (!G2) {
                    v0 = fmaxf(v0, 0.f);  v1 = fmaxf(v1, 0.f);
                    __nv_bfloat16 h0 = __float2bfloat16(v0);
                    __nv_bfloat16 h1 = __float2bfloat16(v1);
                    __nv_bfloat16 l0 = __float2bfloat16(v0 - __bfloat162float(h0));
                    __nv_bfloat16 l1 = __float2bfloat16(v1 - __bfloat162float(h1));
                    size_t base = ((size_t)e * NTOK + m0 + row) * 1024 + colg;
                    *(__nv_bfloat162*)(g_hh + base) = __halves2bfloat162(h0, h1);
                    *(__nv_bfloat162*)(g_hl + base) = __halves2bfloat162(l0, l1);
                } else {
                    float w = s_wt[row];
                    float* o = outp + (size_t)s_tok[row] * 1024 + colg;
                    atomicAdd(o,     w * v0);
                    atomicAdd(o + 1, w * v1);
                }
            }
        }
    }
}

// ---------------------------------------------------------------------------
extern "C" void kernel_launch(void* const* d_in, const int* in_sizes, int n_in,
                              void* d_out, int out_size) {
    const float* x  = (const float*)d_in[0];
    const float* W1 = (const float*)d_in[1];
    const float* b1 = (const float*)d_in[2];
    const float* W2 = (const float*)d_in[3];
    const float* b2 = (const float*)d_in[4];
    const float* Wg = (const float*)d_in[5];
    const float* bg = (const float*)d_in[6];
    float* out = (float*)d_out;

    cudaFuncSetAttribute(moe_mma_kernel<false>,
                         cudaFuncAttributeMaxDynamicSharedMemorySize, SMEM_BYTES);
    cudaFuncSetAttribute(moe_mma_kernel<true>,
                         cudaFuncAttributeMaxDynamicSharedMemorySize, SMEM_BYTES);

    __nv_bfloat16 *w1th, *w1tl, *w2th, *w2tl;
    cudaGetSymbolAddress((void**)&w1th, g_W1Th);
    cudaGetSymbolAddress((void**)&w1tl, g_W1Tl);
    cudaGetSymbolAddress((void**)&w2th, g_W2Th);
    cudaGetSymbolAddress((void**)&w2tl, g_W2Tl);

    zero_kernel<<<(NTOK * DOUT) / 4 / 256, 256>>>(out);
    gate_kernel<<<(NTOK * 32) / 256, 256>>>(x, Wg, bg);
    split_x_kernel<<<(NTOK * DIN) / 4 / 256, 256>>>(x);

    dim3 tg(32, 32, NEXP);
    transpose_split_kernel<<<tg, dim3(32, 8)>>>(W1, w1th, w1tl);
    transpose_split_kernel<<<tg, dim3(32, 8)>>>(W2, w2th, w2tl);

    dim3 grid(DOUT / BN, NTOK / BM, NEXP);
    moe_mma_kernel<false><<<grid, THREADS, SMEM_BYTES>>>(w1th, w1tl, b1, nullptr);
    moe_mma_kernel<true><<<grid, THREADS, SMEM_BYTES>>>(w2th, w2tl, b2, out);
}

// round 6
// speedup vs baseline: 1.5355x; 1.5355x over previous
#include <cuda_runtime.h>
#include <cuda_fp16.h>
#include <cstdint>

#define NEXP 8
#define DIN  1024
#define DOUT 1024
#define NTOK 8192

#define BM 128
#define BN 128
#define BK 32
#define THREADS 256

#define ROWPITCH 80                      /* 32 fp16 = 64B data, padded to 80B */
#define A_TILE_B (128 * ROWPITCH)        /* 10240 */
#define STAGE_B  (3 * A_TILE_B)          /* 30720: Ah, Al, B */
#define NSTAGE   3
#define SMEM_BYTES (NSTAGE * STAGE_B)    /* 92160 -> 2 CTAs/SM */
#define AL_OFF   A_TILE_B
#define B_OFF    (2 * A_TILE_B)

// ---------------- scratch (device globals; no allocation) ----------------
__device__ int    g_cnt[NEXP];
__device__ int    g_tok[NEXP * NTOK];
__device__ float  g_wt [NEXP * NTOK];
__device__ __half g_xh [(size_t)NTOK * DIN];
__device__ __half g_xl [(size_t)NTOK * DIN];
__device__ __half g_hh [(size_t)NEXP * NTOK * DOUT];
__device__ __half g_hl [(size_t)NEXP * NTOK * DOUT];
__device__ __half g_W1T[(size_t)NEXP * DIN * DOUT];   // fp16, transposed [E][N][K]
__device__ __half g_W2T[(size_t)NEXP * DOUT * DOUT];

// ---------------- helpers ----------------
__device__ __forceinline__ uint32_t smem_u32(const void* p) {
    uint32_t a;
    asm("{ .reg .u64 t; cvta.to.shared.u64 t, %1; cvt.u32.u64 %0, t; }" : "=r"(a) : "l"(p));
    return a;
}
__device__ __forceinline__ void cp_async16(uint32_t dst, const void* src) {
    asm volatile("cp.async.cg.shared.global [%0], [%1], 16;" :: "r"(dst), "l"(src) : "memory");
}
#define CP_COMMIT() asm volatile("cp.async.commit_group;" ::: "memory")
#define CP_WAIT1()  asm volatile("cp.async.wait_group 1;" ::: "memory")

__device__ __forceinline__ void mma_f16(float* d, const uint32_t* a, const uint32_t* b) {
    asm volatile(
        "mma.sync.aligned.m16n8k16.row.col.f32.f16.f16.f32 "
        "{%0,%1,%2,%3},{%4,%5,%6,%7},{%8,%9},{%0,%1,%2,%3};"
        : "+f"(d[0]), "+f"(d[1]), "+f"(d[2]), "+f"(d[3])
        : "r"(a[0]), "r"(a[1]), "r"(a[2]), "r"(a[3]), "r"(b[0]), "r"(b[1]));
}
__device__ __forceinline__ void ldmx4(uint32_t* r, uint32_t addr) {
    asm volatile("ldmatrix.sync.aligned.m8n8.x4.shared.b16 {%0,%1,%2,%3}, [%4];"
                 : "=r"(r[0]), "=r"(r[1]), "=r"(r[2]), "=r"(r[3]) : "r"(addr));
}

// ---------------------------------------------------------------------------
__global__ void zero_kernel(float* __restrict__ out) {
    int i = blockIdx.x * blockDim.x + threadIdx.x;
    ((float4*)out)[i] = make_float4(0.f, 0.f, 0.f, 0.f);
    if (blockIdx.x == 0 && threadIdx.x < NEXP) g_cnt[threadIdx.x] = 0;
}

// ---------------------------------------------------------------------------
__global__ void gate_kernel(const float* __restrict__ x,
                            const float* __restrict__ Wg,
                            const float* __restrict__ bg) {
    int warp = (blockIdx.x * blockDim.x + threadIdx.x) >> 5;
    int lane = threadIdx.x & 31;
    if (warp >= NTOK) return;
    const float* xr = x + (size_t)warp * DIN;
    float acc[NEXP];
#pragma unroll
    for (int e = 0; e < NEXP; e++) acc[e] = 0.f;
    for (int kk = 0; kk < DIN / 32; kk++) {
        int k = kk * 32 + lane;
        float xv = xr[k];
        const float* wr = Wg + k * NEXP;
#pragma unroll
        for (int e = 0; e < NEXP; e++) acc[e] += xv * wr[e];
    }
#pragma unroll
    for (int e = 0; e < NEXP; e++)
#pragma unroll
        for (int o = 16; o > 0; o >>= 1)
            acc[e] += __shfl_xor_sync(0xffffffffu, acc[e], o);
    if (lane == 0) {
        float m = -1e30f;
#pragma unroll
        for (int e = 0; e < NEXP; e++) { acc[e] += bg[e]; m = fmaxf(m, acc[e]); }
        float s = 0.f;
#pragma unroll
        for (int e = 0; e < NEXP; e++) { acc[e] = expf(acc[e] - m); s += acc[e]; }
        float inv = 1.f / s;
        int e0 = 0, e1 = -1;
        float v0 = acc[0], v1 = -1.f;
#pragma unroll
        for (int e = 1; e < NEXP; e++) {
            float v = acc[e];
            if (v > v0)      { v1 = v0; e1 = e0; v0 = v; e0 = e; }
            else if (v > v1) { v1 = v;  e1 = e; }
        }
        int p0 = atomicAdd(&g_cnt[e0], 1);
        g_tok[e0 * NTOK + p0] = warp;  g_wt[e0 * NTOK + p0] = v0 * inv;
        int p1 = atomicAdd(&g_cnt[e1], 1);
        g_tok[e1 * NTOK + p1] = warp;  g_wt[e1 * NTOK + p1] = v1 * inv;
    }
}

// ---------------------------------------------------------------------------
// x fp32 -> fp16 hi/lo split (near-exact: residual captured to ~2^-22)
// ---------------------------------------------------------------------------
__global__ void split_x_kernel(const float* __restrict__ x) {
    size_t i = ((size_t)blockIdx.x * blockDim.x + threadIdx.x) * 4;
    float4 v = *(const float4*)(x + i);
    __half h0 = __float2half(v.x), h1 = __float2half(v.y);
    __half h2 = __float2half(v.z), h3 = __float2half(v.w);
    __half l0 = __float2half(v.x - __half2float(h0));
    __half l1 = __float2half(v.y - __half2float(h1));
    __half l2 = __float2half(v.z - __half2float(h2));
    __half l3 = __float2half(v.w - __half2float(h3));
    *(__half2*)(g_xh + i)     = __halves2half2(h0, h1);
    *(__half2*)(g_xh + i + 2) = __halves2half2(h2, h3);
    *(__half2*)(g_xl + i)     = __halves2half2(l0, l1);
    *(__half2*)(g_xl + i + 2) = __halves2half2(l2, l3);
}

// ---------------------------------------------------------------------------
// W [E,K,N] fp32 -> W^T [E,N,K] fp16 (single rounding; rms rel err 2.8e-4)
// ---------------------------------------------------------------------------
__global__ void transpose_half_kernel(const float* __restrict__ W,
                                      __half* __restrict__ WT) {
    __shared__ float t[32][33];
    int e = blockIdx.z;
    const float* Ws = W + ((size_t)e << 20);
    int x0 = blockIdx.x * 32, y0 = blockIdx.y * 32;
    int tx = threadIdx.x, ty = threadIdx.y;
#pragma unroll
    for (int i = 0; i < 32; i += 8)
        t[ty + i][tx] = Ws[(size_t)(y0 + ty + i) * 1024 + x0 + tx];
    __syncthreads();
#pragma unroll
    for (int i = 0; i < 32; i += 8) {
        size_t o = ((size_t)e << 20) + (size_t)(x0 + ty + i) * 1024 + y0 + tx;
        WT[o] = __float2half(t[tx][ty + i]);
    }
}

// ---------------------------------------------------------------------------
// fp16 2-term mma.sync GEMM: 128x128x32 tiles, 3-stage cp.async, 2 CTAs/SM.
// 8 warps = 2(M) x 4(N), warp tile 64x32. Terms: ah*b + al*b.
// ---------------------------------------------------------------------------
template <bool G2>
__global__ __launch_bounds__(THREADS, 2)
void moe_mma_kernel(const __half* __restrict__ Wt,
                    const float* __restrict__ bias,
                    float* __restrict__ outp) {
    extern __shared__ char smem[];
    __shared__ int   s_tok[BM];
    __shared__ float s_wt[BM];
    __shared__ float s_bias[BN];

    const int e   = blockIdx.z;
    const int cnt = g_cnt[e];
    const int m0  = blockIdx.y * BM;
    if (m0 >= cnt) return;
    const int n0  = blockIdx.x * BN;

    const int tid  = threadIdx.x;
    const int wid  = tid >> 5;
    const int lane = tid & 31;

    if (tid < BM) {
        int ok = (m0 + tid) < cnt;
        s_tok[tid] = ok ? g_tok[e * NTOK + m0 + tid] : 0;
        s_wt[tid]  = ok ? g_wt[e * NTOK + m0 + tid] : 0.f;
        s_bias[tid] = bias[e * 1024 + n0 + tid];
    }
    __syncthreads();

    // ---- cp.async geometry: 6 ops/thread/iter ----
    const uint32_t sb = smem_u32(smem);
    const int r0 = tid >> 2;             // 0..63
    const int ch = tid & 3;              // 16B chunk in 64B row

    const __half* pA0;
    const __half* pA1;
    ptrdiff_t dAl;
    if (G2) {
        // unrouted rows (>= cnt) were never written -> zero-init, harmless
        pA0 = g_hh + ((size_t)e * NTOK + m0 + r0) * 1024 + ch * 8;
        pA1 = pA0 + (size_t)64 * 1024;
        dAl = g_hl - g_hh;
    } else {
        pA0 = g_xh + (size_t)s_tok[r0] * 1024 + ch * 8;
        pA1 = g_xh + (size_t)s_tok[r0 + 64] * 1024 + ch * 8;
        dAl = g_xl - g_xh;
    }
    const __half* pB = Wt + (((size_t)e << 10) + n0 + r0) * 1024 + ch * 8;

    const uint32_t sA = sb + r0 * ROWPITCH + ch * 16;
    const uint32_t sB = sb + B_OFF + r0 * ROWPITCH + ch * 16;

    auto issue = [&](int s, int c) {
        const uint32_t so = (uint32_t)(s * STAGE_B);
        const size_t ko = (size_t)c * BK;
        cp_async16(sA + so,                          pA0 + ko);
        cp_async16(sA + so + 64 * ROWPITCH,          pA1 + ko);
        cp_async16(sA + so + AL_OFF,                 pA0 + dAl + ko);
        cp_async16(sA + so + AL_OFF + 64 * ROWPITCH, pA1 + dAl + ko);
        cp_async16(sB + so,                          pB + ko);
        cp_async16(sB + so + 64 * ROWPITCH,          pB + (size_t)64 * 1024 + ko);
    };

    float ac[4][4][4];
#pragma unroll
    for (int a = 0; a < 4; a++)
#pragma unroll
        for (int b = 0; b < 4; b++)
#pragma unroll
            for (int c = 0; c < 4; c++) ac[a][b][c] = 0.f;

    issue(0, 0); CP_COMMIT();
    issue(1, 1); CP_COMMIT();

    const int wm = wid >> 2;             // 0..1 -> m offset 64*wm
    const int wn = wid & 3;              // 0..3 -> n offset 32*wn

    const int aRow  = wm * 64 + (lane & 7) + ((lane >> 3) & 1) * 8;
    const int aKoff = ((lane >> 4) & 1) * 16;
    const int bRow  = wn * 32 + (lane & 7) + ((lane >> 4) & 1) * 8;
    const int bKoff = ((lane >> 3) & 1) * 16;

    const int NITER = DIN / BK;          // 32
    for (int c = 0; c < NITER; c++) {
        const int s = c % NSTAGE;
        CP_WAIT1();
        __syncthreads();
        if (c + 2 < NITER) issue((c + 2) % NSTAGE, c + 2);
        CP_COMMIT();

        const uint32_t stg = sb + s * STAGE_B;
        const uint32_t Ah = stg;
        const uint32_t Al = stg + AL_OFF;
        const uint32_t Bt = stg + B_OFF;

#pragma unroll
        for (int ks = 0; ks < 2; ks++) {
            const uint32_t aoff = (uint32_t)(aRow * ROWPITCH + ks * 32 + aKoff);
            const uint32_t boff = (uint32_t)(bRow * ROWPITCH + ks * 32 + bKoff);
            uint32_t ah[4][4], al[4][4], bf[2][4];
#pragma unroll
            for (int mf = 0; mf < 4; mf++) {
                ldmx4(ah[mf], Ah + aoff + mf * 16 * ROWPITCH);
                ldmx4(al[mf], Al + aoff + mf * 16 * ROWPITCH);
            }
#pragma unroll
            for (int np = 0; np < 2; np++)
                ldmx4(bf[np], Bt + boff + np * 16 * ROWPITCH);
#pragma unroll
            for (int mf = 0; mf < 4; mf++)
#pragma unroll
                for (int nf = 0; nf < 4; nf++)
                    mma_f16(ac[mf][nf], ah[mf], &bf[nf >> 1][(nf & 1) * 2]);
#pragma unroll
            for (int mf = 0; mf < 4; mf++)
#pragma unroll
                for (int nf = 0; nf < 4; nf++)
                    mma_f16(ac[mf][nf], al[mf], &bf[nf >> 1][(nf & 1) * 2]);
        }
    }

    // ---- epilogue: direct from registers (quads cover full 32B sectors) ----
    const int lr = lane >> 2;
    const int lc = (lane & 3) * 2;
#pragma unroll
    for (int mf = 0; mf < 4; mf++) {
#pragma unroll
        for (int nf = 0; nf < 4; nf++) {
            const float* d = ac[mf][nf];
            int col_l = wn * 32 + nf * 8 + lc;
            int colg  = n0 + col_l;
            float bb0 = s_bias[col_l], bb1 = s_bias[col_l + 1];
#pragma unroll
            for (int half = 0; half < 2; half++) {
                int row = wm * 64 + mf * 16 + lr + half * 8;  // local slot
                if (m0 + row >= cnt) continue;
                float v0 = d[half * 2]     + bb0;
                float v1 = d[half * 2 + 1] + bb1;
                if (!G2) {
                    v0 = fmaxf(v0, 0.f);  v1 = fmaxf(v1, 0.f);
                    __half h0 = __float2half(v0);
                    __half h1 = __float2half(v1);
                    __half l0 = __float2half(v0 - __half2float(h0));
                    __half l1 = __float2half(v1 - __half2float(h1));
                    size_t base = ((size_t)e * NTOK + m0 + row) * 1024 + colg;
                    *(__half2*)(g_hh + base) = __halves2half2(h0, h1);
                    *(__half2*)(g_hl + base) = __halves2half2(l0, l1);
                } else {
                    float w = s_wt[row];
                    float* o = outp + (size_t)s_tok[row] * 1024 + colg;
                    atomicAdd(o,     w * v0);
                    atomicAdd(o + 1, w * v1);
                }
            }
        }
    }
}

// ---------------------------------------------------------------------------
extern "C" void kernel_launch(void* const* d_in, const int* in_sizes, int n_in,
                              void* d_out, int out_size) {
    const float* x  = (const float*)d_in[0];
    const float* W1 = (const float*)d_in[1];
    const float* b1 = (const float*)d_in[2];
    const float* W2 = (const float*)d_in[3];
    const float* b2 = (const float*)d_in[4];
    const float* Wg = (const float*)d_in[5];
    const float* bg = (const float*)d_in[6];
    float* out = (float*)d_out;

    cudaFuncSetAttribute(moe_mma_kernel<false>,
                         cudaFuncAttributeMaxDynamicSharedMemorySize, SMEM_BYTES);
    cudaFuncSetAttribute(moe_mma_kernel<true>,
                         cudaFuncAttributeMaxDynamicSharedMemorySize, SMEM_BYTES);

    __half *w1t, *w2t;
    cudaGetSymbolAddress((void**)&w1t, g_W1T);
    cudaGetSymbolAddress((void**)&w2t, g_W2T);

    zero_kernel<<<(NTOK * DOUT) / 4 / 256, 256>>>(out);
    gate_kernel<<<(NTOK * 32) / 256, 256>>>(x, Wg, bg);
    split_x_kernel<<<(NTOK * DIN) / 4 / 256, 256>>>(x);

    dim3 tg(32, 32, NEXP);
    transpose_half_kernel<<<tg, dim3(32, 8)>>>(W1, w1t);
    transpose_half_kernel<<<tg, dim3(32, 8)>>>(W2, w2t);

    dim3 grid(DOUT / BN, NTOK / BM, NEXP);
    moe_mma_kernel<false><<<grid, THREADS, SMEM_BYTES>>>(w1t, b1, nullptr);
    moe_mma_kernel<true><<<grid, THREADS, SMEM_BYTES>>>(w2t, b2, out);
}

// round 7
// speedup vs baseline: 2.3691x; 1.5429x over previous
#include <cuda_runtime.h>
#include <cuda_fp16.h>
#include <cstdint>

#define NEXP 8
#define DIN  1024
#define DOUT 1024
#define NTOK 8192

#define BM 128
#define BN 128
#define BK 32
#define THREADS 256

#define ROWPITCH 80                      /* 32 fp16 = 64B data, padded to 80B */
#define A_TILE_B (128 * ROWPITCH)        /* 10240 */
#define STAGE_B  (2 * A_TILE_B)          /* 20480: A, B */
#define NSTAGE   4
#define SMEM_BYTES (NSTAGE * STAGE_B)    /* 81920 -> 2 CTAs/SM */
#define B_OFF    A_TILE_B

// ---------------- scratch (device globals; no allocation) ----------------
__device__ int    g_cnt[NEXP];
__device__ int    g_tok[NEXP * NTOK];
__device__ float  g_wt [NEXP * NTOK];
__device__ __half g_x16[(size_t)NTOK * DIN];
__device__ __half g_h16[(size_t)NEXP * NTOK * DOUT];
__device__ __half g_W1T[(size_t)NEXP * DIN * DOUT];   // fp16, transposed [E][N][K]
__device__ __half g_W2T[(size_t)NEXP * DOUT * DOUT];

// ---------------- helpers ----------------
__device__ __forceinline__ uint32_t smem_u32(const void* p) {
    uint32_t a;
    asm("{ .reg .u64 t; cvta.to.shared.u64 t, %1; cvt.u32.u64 %0, t; }" : "=r"(a) : "l"(p));
    return a;
}
__device__ __forceinline__ void cp_async16(uint32_t dst, const void* src) {
    asm volatile("cp.async.cg.shared.global [%0], [%1], 16;" :: "r"(dst), "l"(src) : "memory");
}
#define CP_COMMIT() asm volatile("cp.async.commit_group;" ::: "memory")
#define CP_WAIT2()  asm volatile("cp.async.wait_group 2;" ::: "memory")

__device__ __forceinline__ void mma_f16(float* d, const uint32_t* a, const uint32_t* b) {
    asm volatile(
        "mma.sync.aligned.m16n8k16.row.col.f32.f16.f16.f32 "
        "{%0,%1,%2,%3},{%4,%5,%6,%7},{%8,%9},{%0,%1,%2,%3};"
        : "+f"(d[0]), "+f"(d[1]), "+f"(d[2]), "+f"(d[3])
        : "r"(a[0]), "r"(a[1]), "r"(a[2]), "r"(a[3]), "r"(b[0]), "r"(b[1]));
}
__device__ __forceinline__ void ldmx4(uint32_t* r, uint32_t addr) {
    asm volatile("ldmatrix.sync.aligned.m8n8.x4.shared.b16 {%0,%1,%2,%3}, [%4];"
                 : "=r"(r[0]), "=r"(r[1]), "=r"(r[2]), "=r"(r[3]) : "r"(addr));
}

// ---------------------------------------------------------------------------
__global__ void zero_kernel(float* __restrict__ out) {
    int i = blockIdx.x * blockDim.x + threadIdx.x;
    ((float4*)out)[i] = make_float4(0.f, 0.f, 0.f, 0.f);
    if (blockIdx.x == 0 && threadIdx.x < NEXP) g_cnt[threadIdx.x] = 0;
}

// ---------------------------------------------------------------------------
__global__ void gate_kernel(const float* __restrict__ x,
                            const float* __restrict__ Wg,
                            const float* __restrict__ bg) {
    int warp = (blockIdx.x * blockDim.x + threadIdx.x) >> 5;
    int lane = threadIdx.x & 31;
    if (warp >= NTOK) return;
    const float* xr = x + (size_t)warp * DIN;
    float acc[NEXP];
#pragma unroll
    for (int e = 0; e < NEXP; e++) acc[e] = 0.f;
    for (int kk = 0; kk < DIN / 32; kk++) {
        int k = kk * 32 + lane;
        float xv = xr[k];
        const float* wr = Wg + k * NEXP;
#pragma unroll
        for (int e = 0; e < NEXP; e++) acc[e] += xv * wr[e];
    }
#pragma unroll
    for (int e = 0; e < NEXP; e++)
#pragma unroll
        for (int o = 16; o > 0; o >>= 1)
            acc[e] += __shfl_xor_sync(0xffffffffu, acc[e], o);
    if (lane == 0) {
        float m = -1e30f;
#pragma unroll
        for (int e = 0; e < NEXP; e++) { acc[e] += bg[e]; m = fmaxf(m, acc[e]); }
        float s = 0.f;
#pragma unroll
        for (int e = 0; e < NEXP; e++) { acc[e] = expf(acc[e] - m); s += acc[e]; }
        float inv = 1.f / s;
        int e0 = 0, e1 = -1;
        float v0 = acc[0], v1 = -1.f;
#pragma unroll
        for (int e = 1; e < NEXP; e++) {
            float v = acc[e];
            if (v > v0)      { v1 = v0; e1 = e0; v0 = v; e0 = e; }
            else if (v > v1) { v1 = v;  e1 = e; }
        }
        int p0 = atomicAdd(&g_cnt[e0], 1);
        g_tok[e0 * NTOK + p0] = warp;  g_wt[e0 * NTOK + p0] = v0 * inv;
        int p1 = atomicAdd(&g_cnt[e1], 1);
        g_tok[e1 * NTOK + p1] = warp;  g_wt[e1 * NTOK + p1] = v1 * inv;
    }
}

// ---------------------------------------------------------------------------
// x fp32 -> fp16 (single rounding)
// ---------------------------------------------------------------------------
__global__ void convert_x_kernel(const float* __restrict__ x) {
    size_t i = ((size_t)blockIdx.x * blockDim.x + threadIdx.x) * 4;
    float4 v = *(const float4*)(x + i);
    *(__half2*)(g_x16 + i)     = __halves2half2(__float2half(v.x), __float2half(v.y));
    *(__half2*)(g_x16 + i + 2) = __halves2half2(__float2half(v.z), __float2half(v.w));
}

// ---------------------------------------------------------------------------
// W [E,K,N] fp32 -> W^T [E,N,K] fp16 (single rounding)
// ---------------------------------------------------------------------------
__global__ void transpose_half_kernel(const float* __restrict__ W,
                                      __half* __restrict__ WT) {
    __shared__ float t[32][33];
    int e = blockIdx.z;
    const float* Ws = W + ((size_t)e << 20);
    int x0 = blockIdx.x * 32, y0 = blockIdx.y * 32;
    int tx = threadIdx.x, ty = threadIdx.y;
#pragma unroll
    for (int i = 0; i < 32; i += 8)
        t[ty + i][tx] = Ws[(size_t)(y0 + ty + i) * 1024 + x0 + tx];
    __syncthreads();
#pragma unroll
    for (int i = 0; i < 32; i += 8) {
        size_t o = ((size_t)e << 20) + (size_t)(x0 + ty + i) * 1024 + y0 + tx;
        WT[o] = __float2half(t[tx][ty + i]);
    }
}

// ---------------------------------------------------------------------------
// fp16 single-term mma.sync GEMM: 128x128x32 tiles, 4-stage cp.async,
// 2 CTAs/SM. 8 warps = 2(M) x 4(N), warp tile 64x32.
// ---------------------------------------------------------------------------
template <bool G2>
__global__ __launch_bounds__(THREADS, 2)
void moe_mma_kernel(const __half* __restrict__ Wt,
                    const float* __restrict__ bias,
                    float* __restrict__ outp) {
    extern __shared__ char smem[];
    __shared__ int   s_tok[BM];
    __shared__ float s_wt[BM];
    __shared__ float s_bias[BN];

    const int e   = blockIdx.z;
    const int cnt = g_cnt[e];
    const int m0  = blockIdx.y * BM;
    if (m0 >= cnt) return;
    const int n0  = blockIdx.x * BN;

    const int tid  = threadIdx.x;
    const int wid  = tid >> 5;
    const int lane = tid & 31;

    if (tid < BM) {
        int ok = (m0 + tid) < cnt;
        s_tok[tid] = ok ? g_tok[e * NTOK + m0 + tid] : 0;
        s_wt[tid]  = ok ? g_wt[e * NTOK + m0 + tid] : 0.f;
        s_bias[tid] = bias[e * 1024 + n0 + tid];
    }
    __syncthreads();

    // ---- cp.async geometry: 4 ops/thread/iter ----
    const uint32_t sb = smem_u32(smem);
    const int r0 = tid >> 2;             // 0..63
    const int ch = tid & 3;              // 16B chunk in 64B row

    const __half* pA0;
    const __half* pA1;
    if (G2) {
        // unrouted rows (>= cnt) were never written this round but their
        // product is discarded by the cnt guard in the epilogue
        pA0 = g_h16 + ((size_t)e * NTOK + m0 + r0) * 1024 + ch * 8;
        pA1 = pA0 + (size_t)64 * 1024;
    } else {
        pA0 = g_x16 + (size_t)s_tok[r0] * 1024 + ch * 8;
        pA1 = g_x16 + (size_t)s_tok[r0 + 64] * 1024 + ch * 8;
    }
    const __half* pB = Wt + (((size_t)e << 10) + n0 + r0) * 1024 + ch * 8;

    const uint32_t sA = sb + r0 * ROWPITCH + ch * 16;
    const uint32_t sB = sb + B_OFF + r0 * ROWPITCH + ch * 16;

    auto issue = [&](int s, int c) {
        const uint32_t so = (uint32_t)(s * STAGE_B);
        const size_t ko = (size_t)c * BK;
        cp_async16(sA + so,                 pA0 + ko);
        cp_async16(sA + so + 64 * ROWPITCH, pA1 + ko);
        cp_async16(sB + so,                 pB + ko);
        cp_async16(sB + so + 64 * ROWPITCH, pB + (size_t)64 * 1024 + ko);
    };

    float ac[4][4][4];
#pragma unroll
    for (int a = 0; a < 4; a++)
#pragma unroll
        for (int b = 0; b < 4; b++)
#pragma unroll
            for (int c = 0; c < 4; c++) ac[a][b][c] = 0.f;

    issue(0, 0); CP_COMMIT();
    issue(1, 1); CP_COMMIT();
    issue(2, 2); CP_COMMIT();

    const int wm = wid >> 2;             // 0..1 -> m offset 64*wm
    const int wn = wid & 3;              // 0..3 -> n offset 32*wn

    const int aRow  = wm * 64 + (lane & 7) + ((lane >> 3) & 1) * 8;
    const int aKoff = ((lane >> 4) & 1) * 16;
    const int bRow  = wn * 32 + (lane & 7) + ((lane >> 4) & 1) * 8;
    const int bKoff = ((lane >> 3) & 1) * 16;

    const int NITER = DIN / BK;          // 32
    for (int c = 0; c < NITER; c++) {
        const int s = c & 3;
        CP_WAIT2();
        __syncthreads();
        if (c + 3 < NITER) issue((c + 3) & 3, c + 3);
        CP_COMMIT();

        const uint32_t stg = sb + s * STAGE_B;
        const uint32_t At = stg;
        const uint32_t Bt = stg + B_OFF;

#pragma unroll
        for (int ks = 0; ks < 2; ks++) {
            const uint32_t aoff = (uint32_t)(aRow * ROWPITCH + ks * 32 + aKoff);
            const uint32_t boff = (uint32_t)(bRow * ROWPITCH + ks * 32 + bKoff);
            uint32_t af[4][4], bf[2][4];
#pragma unroll
            for (int mf = 0; mf < 4; mf++)
                ldmx4(af[mf], At + aoff + mf * 16 * ROWPITCH);
#pragma unroll
            for (int np = 0; np < 2; np++)
                ldmx4(bf[np], Bt + boff + np * 16 * ROWPITCH);
#pragma unroll
            for (int mf = 0; mf < 4; mf++)
#pragma unroll
                for (int nf = 0; nf < 4; nf++)
                    mma_f16(ac[mf][nf], af[mf], &bf[nf >> 1][(nf & 1) * 2]);
        }
    }

    // ---- epilogue: direct from registers (quads cover full 32B sectors) ----
    const int lr = lane >> 2;
    const int lc = (lane & 3) * 2;
#pragma unroll
    for (int mf = 0; mf < 4; mf++) {
#pragma unroll
        for (int nf = 0; nf < 4; nf++) {
            const float* d = ac[mf][nf];
            int col_l = wn * 32 + nf * 8 + lc;
            int colg  = n0 + col_l;
            float bb0 = s_bias[col_l], bb1 = s_bias[col_l + 1];
#pragma unroll
            for (int half = 0; half < 2; half++) {
                int row = wm * 64 + mf * 16 + lr + half * 8;  // local slot
                if (m0 + row >= cnt) continue;
                float v0 = d[half * 2]     + bb0;
                float v1 = d[half * 2 + 1] + bb1;
                if (!G2) {
                    v0 = fmaxf(v0, 0.f);  v1 = fmaxf(v1, 0.f);
                    size_t base = ((size_t)e * NTOK + m0 + row) * 1024 + colg;
                    *(__half2*)(g_h16 + base) =
                        __halves2half2(__float2half(v0), __float2half(v1));
                } else {
                    float w = s_wt[row];
                    float* o = outp + (size_t)s_tok[row] * 1024 + colg;
                    atomicAdd(o,     w * v0);
                    atomicAdd(o + 1, w * v1);
                }
            }
        }
    }
}

// ---------------------------------------------------------------------------
extern "C" void kernel_launch(void* const* d_in, const int* in_sizes, int n_in,
                              void* d_out, int out_size) {
    const float* x  = (const float*)d_in[0];
    const float* W1 = (const float*)d_in[1];
    const float* b1 = (const float*)d_in[2];
    const float* W2 = (const float*)d_in[3];
    const float* b2 = (const float*)d_in[4];
    const float* Wg = (const float*)d_in[5];
    const float* bg = (const float*)d_in[6];
    float* out = (float*)d_out;

    cudaFuncSetAttribute(moe_mma_kernel<false>,
                         cudaFuncAttributeMaxDynamicSharedMemorySize, SMEM_BYTES);
    cudaFuncSetAttribute(moe_mma_kernel<true>,
                         cudaFuncAttributeMaxDynamicSharedMemorySize, SMEM_BYTES);

    __half *w1t, *w2t;
    cudaGetSymbolAddress((void**)&w1t, g_W1T);
    cudaGetSymbolAddress((void**)&w2t, g_W2T);

    zero_kernel<<<(NTOK * DOUT) / 4 / 256, 256>>>(out);
    gate_kernel<<<(NTOK * 32) / 256, 256>>>(x, Wg, bg);
    convert_x_kernel<<<(NTOK * DIN) / 4 / 256, 256>>>(x);

    dim3 tg(32, 32, NEXP);
    transpose_half_kernel<<<tg, dim3(32, 8)>>>(W1, w1t);
    transpose_half_kernel<<<tg, dim3(32, 8)>>>(W2, w2t);

    dim3 grid(DOUT / BN, NTOK / BM, NEXP);
    moe_mma_kernel<false><<<grid, THREADS, SMEM_BYTES>>>(w1t, b1, nullptr);
    moe_mma_kernel<true><<<grid, THREADS, SMEM_BYTES>>>(w2t, b2, out);
}